// round 13
// baseline (speedup 1.0000x reference)
#include <cuda_runtime.h>
#include <cuda_fp16.h>
#include <cstdint>

#define IN_CH   768
#define OUT_ROW 1536
#define BM      128
#define BN      128
#define BK      64
#define NCHUNK  12          // 768/64

// smem: [0,1024) bias | 2 stages of 32768B: A 16K | B 16K
#define STGB     32768
#define SM_STG(s) (1024 + (s)*STGB)
#define OFF_B    16384
#define SMEM_TOTAL (1024 + 2*STGB)   // 66560 -> 2 CTAs/SM (256 thr)

#define SWZ(o) ((o) ^ (((o) >> 3) & 0x70))

// Pre-converted fp16 activations, SW128-swizzled, layout == smem A block:
// [mod 3][mtile 128][kchunk 12][128 rows][128 B]
__device__ __align__(128) unsigned char g_Ascr[3*128*12*16384];
// Pre-converted fp16 weights, layout == smem B block:
// [mod 3][ntile 4][kchunk 12][128 rows][128 B]
__device__ __align__(128) unsigned char g_Bscr[3*4*12*16384];

static __device__ __forceinline__ uint32_t s2u(const void* p) {
    uint32_t a;
    asm("{ .reg .u64 t; cvta.to.shared.u64 t, %1; cvt.u32.u64 %0, t; }" : "=r"(a) : "l"(p));
    return a;
}
static __device__ __forceinline__ void ldsm4(uint32_t* r, uint32_t addr) {
    asm volatile("ldmatrix.sync.aligned.m8n8.x4.shared.b16 {%0,%1,%2,%3}, [%4];"
                 : "=r"(r[0]), "=r"(r[1]), "=r"(r[2]), "=r"(r[3]) : "r"(addr));
}
static __device__ __forceinline__ void mma16816(float* c, const uint32_t* a, const uint32_t* b) {
    asm volatile("mma.sync.aligned.m16n8k16.row.col.f32.f16.f16.f32 "
                 "{%0,%1,%2,%3}, {%4,%5,%6,%7}, {%8,%9}, {%0,%1,%2,%3};"
                 : "+f"(c[0]), "+f"(c[1]), "+f"(c[2]), "+f"(c[3])
                 : "r"(a[0]), "r"(a[1]), "r"(a[2]), "r"(a[3]), "r"(b[0]), "r"(b[1]));
}
static __device__ __forceinline__ void cp16(uint32_t dst, const void* src) {
    asm volatile("cp.async.cg.shared.global [%0], [%1], 16;" :: "r"(dst), "l"(src) : "memory");
}
#define CP_COMMIT asm volatile("cp.async.commit_group;" ::: "memory")
#define CP_WAIT0  asm volatile("cp.async.wait_group 0;" ::: "memory")

// ============ kernel 0: activation conversion fp32 -> fp16 (swizzled) ============
__global__ __launch_bounds__(256)
void caps_convx(const float* __restrict__ x_img,
                const float* __restrict__ x_capt,
                const float* __restrict__ x_dct)
{
    int gt  = blockIdx.x * 256 + threadIdx.x;     // [0, 4718592)
    int mod = gt / 1572864;
    int r   = gt % 1572864;
    int b   = r / 96;                             // batch row [0,16384)
    int k8  = r % 96;                             // 8-float k group
    const float* X = (mod == 0) ? x_img : (mod == 1) ? x_capt : x_dct;
    const float4* src = (const float4*)(X + (size_t)b * IN_CH + k8 * 8);
    float4 p = src[0], q = src[1];
    __half2 h0 = __float22half2_rn(make_float2(p.x, p.y));
    __half2 h1 = __float22half2_rn(make_float2(p.z, p.w));
    __half2 h2 = __float22half2_rn(make_float2(q.x, q.y));
    __half2 h3 = __float22half2_rn(make_float2(q.z, q.w));
    int mtile = b >> 7, rloc = b & 127;
    int kch = k8 >> 3, cell = k8 & 7;
    uint32_t off = SWZ((uint32_t)(rloc * 128 + cell * 16));
    unsigned char* dst = g_Ascr + (size_t)(((mod * 128 + mtile) * 12) + kch) * 16384 + off;
    *(uint4*)dst = make_uint4(*(uint32_t*)&h0, *(uint32_t*)&h1, *(uint32_t*)&h2, *(uint32_t*)&h3);
}

// ============ kernel 1: weight conversion fp32 -> fp16 (swizzled) ============
__global__ __launch_bounds__(256)
void caps_convw(const float* __restrict__ w_img,
                const float* __restrict__ w_capt,
                const float* __restrict__ w_dct)
{
    int gt  = blockIdx.x * 256 + threadIdx.x;     // [0, 147456)
    int mod = gt / 49152;
    int r   = gt % 49152;
    int n   = r / 96;                             // output col within modality [0,512)
    int k8  = r % 96;
    const float* W = (mod == 0) ? w_img : (mod == 1) ? w_capt : w_dct;
    int wrow = ((n & 7) << 6) | (n >> 3);         // W row for col n = r*8 + c
    const float4* src = (const float4*)(W + (size_t)wrow * IN_CH + k8 * 8);
    float4 p = src[0], q = src[1];
    __half2 h0 = __float22half2_rn(make_float2(p.x, p.y));
    __half2 h1 = __float22half2_rn(make_float2(p.z, p.w));
    __half2 h2 = __float22half2_rn(make_float2(q.x, q.y));
    __half2 h3 = __float22half2_rn(make_float2(q.z, q.w));
    int ntile = n >> 7, rloc = n & 127;
    int kch = k8 >> 3, cell = k8 & 7;
    uint32_t off = SWZ((uint32_t)(rloc * 128 + cell * 16));
    unsigned char* dst = g_Bscr + (size_t)((mod * 4 + ntile) * 12 + kch) * 16384 + off;
    *(uint4*)dst = make_uint4(*(uint32_t*)&h0, *(uint32_t*)&h1, *(uint32_t*)&h2, *(uint32_t*)&h3);
}

// ============ kernel 2: fp16 mma.sync GEMM + bias + squash ============
// 8 warps, warp tile 32x64 (wm 4 x wn 2), 2 CTAs/SM -> 4 warps/SMSP
__global__ __launch_bounds__(256, 2)
void caps_gemm(const float* __restrict__ b_img,
               const float* __restrict__ b_capt,
               const float* __restrict__ b_dct,
               float* __restrict__ out)
{
    extern __shared__ __align__(1024) unsigned char smem[];
    const uint32_t sb = s2u(smem);
    float* biasS = (float*)smem;

    const int tid  = threadIdx.x;
    const int lane = tid & 31;
    const int w    = tid >> 5;
    const int wm   = w & 3;            // 4 warps over M (32 rows each)
    const int wn   = w >> 2;           // 2 warps over N (64 cols each)
    const int b0   = blockIdx.y * BM;  // mtile on y
    const int n0   = blockIdx.x * BN;  // ntile on x (4 adjacent CTAs share A slab)
    const int mod  = blockIdx.z;

    const float* Bv = (mod == 0) ? b_img : (mod == 1) ? b_capt : b_dct;
    if (tid < BN) { int n = n0 + tid; biasS[tid] = Bv[((n & 7) << 6) + (n >> 3)]; }

    // gmem sources (layouts identical to smem blocks)
    const unsigned char* aG = g_Ascr + (size_t)((mod * 128 + blockIdx.y) * 12) * 16384;
    const unsigned char* bG = g_Bscr + (size_t)((mod * 4 + blockIdx.x) * 12) * 16384;

    // ldsm consumer bases
    const uint32_t aXor  = (uint32_t)((lane & 7) << 4);
    const uint32_t aRowB = (uint32_t)((wm * 32 + (lane & 15)) * 128);
    const uint32_t aCell = (uint32_t)(((lane >> 4) & 1) * 16);
    const uint32_t bXor  = aXor;
    const uint32_t bRowB = (uint32_t)((wn * 64 + (lane & 7) + ((lane & 16) ? 8 : 0)) * 128);
    const uint32_t bCell = (uint32_t)((lane & 8) ? 16 : 0);

    float acc[2][8][4];
    #pragma unroll
    for (int i = 0; i < 2; ++i)
        #pragma unroll
        for (int j = 0; j < 8; ++j)
            #pragma unroll
            for (int k = 0; k < 4; ++k) acc[i][j][k] = 0.f;

    // ---- prologue: stage 0 <- chunk 0 (4+4 cp16 per thread, 256 threads) ----
    {
        uint32_t dst = sb + SM_STG(0);
        #pragma unroll
        for (int j = 0; j < 4; ++j) {
            cp16(dst + tid * 16 + j * 4096,         aG + tid * 16 + j * 4096);
            cp16(dst + OFF_B + tid * 16 + j * 4096, bG + tid * 16 + j * 4096);
        }
        CP_COMMIT;
    }
    CP_WAIT0;
    __syncthreads();

    for (int i = 0; i < NCHUNK; ++i) {
        // ---- issue cp for chunk i+1 into the other stage ----
        if (i + 1 < NCHUNK) {
            uint32_t dst = sb + SM_STG((i + 1) & 1);
            const unsigned char* sa = aG + (size_t)(i + 1) * 16384;
            const unsigned char* sbp = bG + (size_t)(i + 1) * 16384;
            #pragma unroll
            for (int j = 0; j < 4; ++j) {
                cp16(dst + tid * 16 + j * 4096,         sa + tid * 16 + j * 4096);
                cp16(dst + OFF_B + tid * 16 + j * 4096, sbp + tid * 16 + j * 4096);
            }
            CP_COMMIT;
        }

        // ---- compute chunk i from stage i&1 ----
        const uint32_t stg = sb + SM_STG(i & 1);
        #pragma unroll
        for (int st = 0; st < 4; ++st) {
            const uint32_t sx = (uint32_t)(st << 5);
            uint32_t af[2][4];
            #pragma unroll
            for (int mt = 0; mt < 2; ++mt)
                ldsm4(af[mt], stg + aRowB + mt * 2048 + ((sx + aCell) ^ aXor));
            #pragma unroll
            for (int g = 0; g < 4; ++g) {
                uint32_t bf[4];
                ldsm4(bf, stg + OFF_B + bRowB + g * 2048 + ((sx + bCell) ^ bXor));
                #pragma unroll
                for (int half = 0; half < 2; ++half) {
                    const uint32_t* BH = &bf[half * 2];
                    #pragma unroll
                    for (int mt = 0; mt < 2; ++mt)
                        mma16816(acc[mt][2 * g + half], af[mt], BH);
                }
            }
        }

        if (i + 1 < NCHUNK) {
            CP_WAIT0;            // chunk i+1 landed (issued a full compute ago)
            __syncthreads();
        }
    }

    // ---- epilogue: bias + squash (8-col group == one n8 tile) ----
    const int t4 = lane & 3, g8 = lane >> 2;
    #pragma unroll
    for (int mt = 0; mt < 2; ++mt) {
        const int row0 = b0 + wm * 32 + mt * 16 + g8;
        #pragma unroll
        for (int nt = 0; nt < 8; ++nt) {
            float* c = acc[mt][nt];
            const int cl = wn * 64 + nt * 8 + 2 * t4;
            const float bx = biasS[cl], by = biasS[cl + 1];
            float u0 = c[0] + bx, u1 = c[1] + by;
            float u2 = c[2] + bx, u3 = c[3] + by;
            float s0 = u0 * u0 + u1 * u1;
            float s1 = u2 * u2 + u3 * u3;
            s0 += __shfl_xor_sync(0xffffffffu, s0, 1);
            s0 += __shfl_xor_sync(0xffffffffu, s0, 2);
            s1 += __shfl_xor_sync(0xffffffffu, s1, 1);
            s1 += __shfl_xor_sync(0xffffffffu, s1, 2);
            float sc0 = s0 / ((1.0f + s0) * sqrtf(s0 + 1e-7f));
            float sc1 = s1 / ((1.0f + s1) * sqrtf(s1 + 1e-7f));
            float* p0 = out + (size_t)row0 * OUT_ROW + mod * 512 + n0 + cl;
            float* p1 = p0 + 8 * OUT_ROW;
            *(float2*)p0 = make_float2(u0 * sc0, u1 * sc0);
            *(float2*)p1 = make_float2(u2 * sc1, u3 * sc1);
        }
    }
}

extern "C" void kernel_launch(void* const* d_in, const int* in_sizes, int n_in,
                              void* d_out, int out_size)
{
    const float* x_img  = (const float*)d_in[0];
    const float* x_capt = (const float*)d_in[1];
    const float* x_dct  = (const float*)d_in[2];
    const float* w_img  = (const float*)d_in[3];
    const float* b_img  = (const float*)d_in[4];
    const float* w_capt = (const float*)d_in[5];
    const float* b_capt = (const float*)d_in[6];
    const float* w_dct  = (const float*)d_in[7];
    const float* b_dct  = (const float*)d_in[8];
    float* out = (float*)d_out;

    cudaFuncSetAttribute(caps_gemm, cudaFuncAttributeMaxDynamicSharedMemorySize, SMEM_TOTAL);

    caps_convx<<<18432, 256>>>(x_img, x_capt, x_dct);
    caps_convw<<<576, 256>>>(w_img, w_capt, w_dct);

    dim3 grid(512 / BN, 16384 / BM, 3);   // (4, 128, 3): x=ntile shares A slab in L2
    caps_gemm<<<grid, 256, SMEM_TOTAL>>>(b_img, b_capt, b_dct, out);
}

// round 14
// speedup vs baseline: 1.0482x; 1.0482x over previous
#include <cuda_runtime.h>
#include <cuda_fp16.h>
#include <cstdint>

#define IN_CH   768
#define OUT_ROW 1536
#define BM      128
#define BN      128
#define BK      64
#define NCHUNK  12          // 768/64
#define NT      1536        // total tiles: 128 mtile * 4 ntile * 3 mod
#define GRID_P  444         // 148 SMs * 3 CTAs

// smem: [0,512) bias | [512,516) nextT | 2 stages of 32768B @1024: A 16K | B 16K
#define STGB     32768
#define SM_STG(s) (1024 + (s)*STGB)
#define OFF_B    16384
#define SMEM_TOTAL (1024 + 2*STGB)   // 66560 -> 3 CTAs/SM

#define SWZ(o) ((o) ^ (((o) >> 3) & 0x70))

// Pre-converted fp16 activations, SW128-swizzled, layout == smem A block:
// [mod 3][mtile 128][kchunk 12][128 rows][128 B]
__device__ __align__(128) unsigned char g_Ascr[3*128*12*16384];
// Pre-converted fp16 weights, layout == smem B block:
// [mod 3][ntile 4][kchunk 12][128 rows][128 B]
__device__ __align__(128) unsigned char g_Bscr[3*4*12*16384];
// work-stealing counter (reset by caps_convw every launch/replay)
__device__ int g_ctr;

static __device__ __forceinline__ uint32_t s2u(const void* p) {
    uint32_t a;
    asm("{ .reg .u64 t; cvta.to.shared.u64 t, %1; cvt.u32.u64 %0, t; }" : "=r"(a) : "l"(p));
    return a;
}
static __device__ __forceinline__ void ldsm4(uint32_t* r, uint32_t addr) {
    asm volatile("ldmatrix.sync.aligned.m8n8.x4.shared.b16 {%0,%1,%2,%3}, [%4];"
                 : "=r"(r[0]), "=r"(r[1]), "=r"(r[2]), "=r"(r[3]) : "r"(addr));
}
static __device__ __forceinline__ void mma16816(float* c, const uint32_t* a, const uint32_t* b) {
    asm volatile("mma.sync.aligned.m16n8k16.row.col.f32.f16.f16.f32 "
                 "{%0,%1,%2,%3}, {%4,%5,%6,%7}, {%8,%9}, {%0,%1,%2,%3};"
                 : "+f"(c[0]), "+f"(c[1]), "+f"(c[2]), "+f"(c[3])
                 : "r"(a[0]), "r"(a[1]), "r"(a[2]), "r"(a[3]), "r"(b[0]), "r"(b[1]));
}
static __device__ __forceinline__ void cp16(uint32_t dst, const void* src) {
    asm volatile("cp.async.cg.shared.global [%0], [%1], 16;" :: "r"(dst), "l"(src) : "memory");
}
#define CP_COMMIT asm volatile("cp.async.commit_group;" ::: "memory")
#define CP_WAIT0  asm volatile("cp.async.wait_group 0;" ::: "memory")

// ============ kernel 0: activation conversion fp32 -> fp16 (swizzled) ============
__global__ __launch_bounds__(256)
void caps_convx(const float* __restrict__ x_img,
                const float* __restrict__ x_capt,
                const float* __restrict__ x_dct)
{
    int gt  = blockIdx.x * 256 + threadIdx.x;     // [0, 4718592)
    int mod = gt / 1572864;
    int r   = gt % 1572864;
    int b   = r / 96;                             // batch row [0,16384)
    int k8  = r % 96;                             // 8-float k group
    const float* X = (mod == 0) ? x_img : (mod == 1) ? x_capt : x_dct;
    const float4* src = (const float4*)(X + (size_t)b * IN_CH + k8 * 8);
    float4 p = src[0], q = src[1];
    __half2 h0 = __float22half2_rn(make_float2(p.x, p.y));
    __half2 h1 = __float22half2_rn(make_float2(p.z, p.w));
    __half2 h2 = __float22half2_rn(make_float2(q.x, q.y));
    __half2 h3 = __float22half2_rn(make_float2(q.z, q.w));
    int mtile = b >> 7, rloc = b & 127;
    int kch = k8 >> 3, cell = k8 & 7;
    uint32_t off = SWZ((uint32_t)(rloc * 128 + cell * 16));
    unsigned char* dst = g_Ascr + (size_t)(((mod * 128 + mtile) * 12) + kch) * 16384 + off;
    *(uint4*)dst = make_uint4(*(uint32_t*)&h0, *(uint32_t*)&h1, *(uint32_t*)&h2, *(uint32_t*)&h3);
}

// ============ kernel 1: weight conversion fp32 -> fp16 (swizzled) + counter reset ============
__global__ __launch_bounds__(256)
void caps_convw(const float* __restrict__ w_img,
                const float* __restrict__ w_capt,
                const float* __restrict__ w_dct)
{
    if (blockIdx.x == 0 && threadIdx.x == 0) g_ctr = GRID_P;   // reset work counter
    int gt  = blockIdx.x * 256 + threadIdx.x;     // [0, 147456)
    int mod = gt / 49152;
    int r   = gt % 49152;
    int n   = r / 96;                             // output col within modality [0,512)
    int k8  = r % 96;
    const float* W = (mod == 0) ? w_img : (mod == 1) ? w_capt : w_dct;
    int wrow = ((n & 7) << 6) | (n >> 3);         // W row for col n = r*8 + c
    const float4* src = (const float4*)(W + (size_t)wrow * IN_CH + k8 * 8);
    float4 p = src[0], q = src[1];
    __half2 h0 = __float22half2_rn(make_float2(p.x, p.y));
    __half2 h1 = __float22half2_rn(make_float2(p.z, p.w));
    __half2 h2 = __float22half2_rn(make_float2(q.x, q.y));
    __half2 h3 = __float22half2_rn(make_float2(q.z, q.w));
    int ntile = n >> 7, rloc = n & 127;
    int kch = k8 >> 3, cell = k8 & 7;
    uint32_t off = SWZ((uint32_t)(rloc * 128 + cell * 16));
    unsigned char* dst = g_Bscr + (size_t)((mod * 4 + ntile) * 12 + kch) * 16384 + off;
    *(uint4*)dst = make_uint4(*(uint32_t*)&h0, *(uint32_t*)&h1, *(uint32_t*)&h2, *(uint32_t*)&h3);
}

// tile decode: t in [0, NT): mod = t/512, mtile = (t%512)>>2, ntile = t&3
static __device__ __forceinline__ void decode_tile(int t,
    const unsigned char*& aG, const unsigned char*& bG, int& b0, int& n0, int& mod)
{
    mod = t / 512;
    int rem = t - mod * 512;
    int mtile = rem >> 2, ntile = rem & 3;
    aG = g_Ascr + (size_t)((mod * 128 + mtile) * 12) * 16384;
    bG = g_Bscr + (size_t)((mod * 4 + ntile) * 12) * 16384;
    b0 = mtile * BM;
    n0 = ntile * BN;
}

// ============ kernel 2: persistent fp16 mma.sync GEMM + bias + squash ============
// 4 warps, warp tile 64x64, 3 CTAs/SM, 2-stage pipeline, atomic work-stealing
__global__ __launch_bounds__(128, 3)
void caps_gemm(const float* __restrict__ b_img,
               const float* __restrict__ b_capt,
               const float* __restrict__ b_dct,
               float* __restrict__ out)
{
    extern __shared__ __align__(1024) unsigned char smem[];
    const uint32_t sb = s2u(smem);
    float* biasS = (float*)smem;
    volatile int* nextTS = (volatile int*)(smem + 512);

    const int tid  = threadIdx.x;
    const int lane = tid & 31;
    const int w    = tid >> 5;
    const int wm   = w & 1;            // 2 warps over M (64 rows each)
    const int wn   = w >> 1;           // 2 warps over N (64 cols each)

    // ldsm consumer bases (tile-independent)
    const uint32_t aXor  = (uint32_t)((lane & 7) << 4);
    const uint32_t aRowB = (uint32_t)((wm * 64 + (lane & 15)) * 128);
    const uint32_t aCell = (uint32_t)(((lane >> 4) & 1) * 16);
    const uint32_t bXor  = aXor;
    const uint32_t bRowB = (uint32_t)((wn * 64 + (lane & 7) + ((lane & 16) ? 8 : 0)) * 128);
    const uint32_t bCell = (uint32_t)((lane & 8) ? 16 : 0);

    int t = blockIdx.x;                // first tile statically assigned
    const unsigned char *aG, *bG;
    int b0, n0, mod;
    decode_tile(t, aG, bG, b0, n0, mod);
    {
        const float* Bv = (mod == 0) ? b_img : (mod == 1) ? b_capt : b_dct;
        int n = n0 + tid; biasS[tid] = Bv[((n & 7) << 6) + (n >> 3)];
    }

    // ---- prologue: stage 0 <- chunk 0 of first tile ----
    {
        uint32_t dst = sb + SM_STG(0);
        #pragma unroll
        for (int j = 0; j < 8; ++j) {
            cp16(dst + tid * 16 + j * 2048,         aG + tid * 16 + j * 2048);
            cp16(dst + OFF_B + tid * 16 + j * 2048, bG + tid * 16 + j * 2048);
        }
        CP_COMMIT;
    }
    CP_WAIT0;
    __syncthreads();

    int stage = 0;
    for (;;) {
        float acc[4][8][4];
        #pragma unroll
        for (int i = 0; i < 4; ++i)
            #pragma unroll
            for (int j = 0; j < 8; ++j)
                #pragma unroll
                for (int k = 0; k < 4; ++k) acc[i][j][k] = 0.f;

        int nt = NT;   // next tile id, read at chunk 11

        for (int i = 0; i < NCHUNK; ++i) {
            // grab next tile id early; becomes visible via chunk-boundary syncs
            if (i == 0 && tid == 0) *nextTS = atomicAdd(&g_ctr, 1);

            // ---- issue cp for next chunk (or next tile's chunk 0) ----
            bool issued = false;
            if (i + 1 < NCHUNK) {
                uint32_t dst = sb + SM_STG(stage ^ 1);
                const unsigned char* sa = aG + (size_t)(i + 1) * 16384;
                const unsigned char* sbp = bG + (size_t)(i + 1) * 16384;
                #pragma unroll
                for (int j = 0; j < 8; ++j) {
                    cp16(dst + tid * 16 + j * 2048,         sa + tid * 16 + j * 2048);
                    cp16(dst + OFF_B + tid * 16 + j * 2048, sbp + tid * 16 + j * 2048);
                }
                CP_COMMIT;
                issued = true;
            } else {
                nt = *nextTS;
                if (nt < NT) {
                    const unsigned char *aN, *bN; int db0, dn0, dmod;
                    decode_tile(nt, aN, bN, db0, dn0, dmod);
                    uint32_t dst = sb + SM_STG(stage ^ 1);
                    #pragma unroll
                    for (int j = 0; j < 8; ++j) {
                        cp16(dst + tid * 16 + j * 2048,         aN + tid * 16 + j * 2048);
                        cp16(dst + OFF_B + tid * 16 + j * 2048, bN + tid * 16 + j * 2048);
                    }
                    CP_COMMIT;
                    issued = true;
                }
            }

            // ---- compute chunk i from current stage ----
            const uint32_t stg = sb + SM_STG(stage);
            #pragma unroll
            for (int st = 0; st < 4; ++st) {
                const uint32_t sx = (uint32_t)(st << 5);
                uint32_t af[4][4];
                #pragma unroll
                for (int mt = 0; mt < 4; ++mt)
                    ldsm4(af[mt], stg + aRowB + mt * 2048 + ((sx + aCell) ^ aXor));
                #pragma unroll
                for (int g = 0; g < 4; ++g) {
                    uint32_t bf[4];
                    ldsm4(bf, stg + OFF_B + bRowB + g * 2048 + ((sx + bCell) ^ bXor));
                    #pragma unroll
                    for (int half = 0; half < 2; ++half) {
                        const uint32_t* BH = &bf[half * 2];
                        #pragma unroll
                        for (int mt = 0; mt < 4; ++mt)
                            mma16816(acc[mt][2 * g + half], af[mt], BH);
                    }
                }
            }

            if (issued) {
                CP_WAIT0;            // next buffer landed
                __syncthreads();
                stage ^= 1;
            }
        }

        // ---- epilogue: bias + squash (8-col group == one n8 tile) ----
        const int t4 = lane & 3, g8 = lane >> 2;
        #pragma unroll
        for (int mt = 0; mt < 4; ++mt) {
            const int row0 = b0 + wm * 64 + mt * 16 + g8;
            #pragma unroll
            for (int ntj = 0; ntj < 8; ++ntj) {
                float* c = acc[mt][ntj];
                const int cl = wn * 64 + ntj * 8 + 2 * t4;
                const float bx = biasS[cl], by = biasS[cl + 1];
                float u0 = c[0] + bx, u1 = c[1] + by;
                float u2 = c[2] + bx, u3 = c[3] + by;
                float s0 = u0 * u0 + u1 * u1;
                float s1 = u2 * u2 + u3 * u3;
                s0 += __shfl_xor_sync(0xffffffffu, s0, 1);
                s0 += __shfl_xor_sync(0xffffffffu, s0, 2);
                s1 += __shfl_xor_sync(0xffffffffu, s1, 1);
                s1 += __shfl_xor_sync(0xffffffffu, s1, 2);
                float sc0 = s0 / ((1.0f + s0) * sqrtf(s0 + 1e-7f));
                float sc1 = s1 / ((1.0f + s1) * sqrtf(s1 + 1e-7f));
                float* p0 = out + (size_t)row0 * OUT_ROW + mod * 512 + n0 + cl;
                float* p1 = p0 + 8 * OUT_ROW;
                *(float2*)p0 = make_float2(u0 * sc0, u1 * sc0);
                *(float2*)p1 = make_float2(u2 * sc1, u3 * sc1);
            }
        }

        if (nt >= NT) break;
        __syncthreads();               // all epilogue bias reads done before rewrite
        t = nt;
        decode_tile(t, aG, bG, b0, n0, mod);
        {
            const float* Bv = (mod == 0) ? b_img : (mod == 1) ? b_capt : b_dct;
            int n = n0 + tid; biasS[tid] = Bv[((n & 7) << 6) + (n >> 3)];
        }
        // stage already points at this tile's chunk 0 (prefetched + waited above)
    }
}

extern "C" void kernel_launch(void* const* d_in, const int* in_sizes, int n_in,
                              void* d_out, int out_size)
{
    const float* x_img  = (const float*)d_in[0];
    const float* x_capt = (const float*)d_in[1];
    const float* x_dct  = (const float*)d_in[2];
    const float* w_img  = (const float*)d_in[3];
    const float* b_img  = (const float*)d_in[4];
    const float* w_capt = (const float*)d_in[5];
    const float* b_capt = (const float*)d_in[6];
    const float* w_dct  = (const float*)d_in[7];
    const float* b_dct  = (const float*)d_in[8];
    float* out = (float*)d_out;

    cudaFuncSetAttribute(caps_gemm, cudaFuncAttributeMaxDynamicSharedMemorySize, SMEM_TOTAL);

    caps_convw<<<576, 256>>>(w_img, w_capt, w_dct);    // also resets g_ctr
    caps_convx<<<18432, 256>>>(x_img, x_capt, x_dct);

    caps_gemm<<<GRID_P, 128, SMEM_TOTAL>>>(b_img, b_capt, b_dct, out);
}

// round 15
// speedup vs baseline: 1.0677x; 1.0186x over previous
#include <cuda_runtime.h>
#include <cuda_fp16.h>
#include <cstdint>

#define IN_CH   768
#define OUT_ROW 1536
#define BM      128
#define BN      128
#define BK      64
#define NCHUNK  12          // 768/64
#define NT      1536        // total tiles: 128 mtile * 4 ntile * 3 mod
#define GRID_P  444         // 148 SMs * 3 CTAs

// smem: [0,512) bias cur | [512,1024) bias next | [1024,1028) nextT | stages @2048
#define STGB     32768
#define SM_STG(s) (2048 + (s)*STGB)
#define OFF_B    16384
#define SMEM_TOTAL (2048 + 2*STGB)   // 67584 -> 3 CTAs/SM

#define SWZ(o) ((o) ^ (((o) >> 3) & 0x70))

// Pre-converted fp16 activations, SW128-swizzled, layout == smem A block:
// [mod 3][mtile 128][kchunk 12][128 rows][128 B]
__device__ __align__(128) unsigned char g_Ascr[3*128*12*16384];
// Pre-converted fp16 weights, layout == smem B block:
// [mod 3][ntile 4][kchunk 12][128 rows][128 B]
__device__ __align__(128) unsigned char g_Bscr[3*4*12*16384];
// work-stealing counter (reset by conv kernel every launch/replay)
__device__ int g_ctr;

static __device__ __forceinline__ uint32_t s2u(const void* p) {
    uint32_t a;
    asm("{ .reg .u64 t; cvta.to.shared.u64 t, %1; cvt.u32.u64 %0, t; }" : "=r"(a) : "l"(p));
    return a;
}
static __device__ __forceinline__ void ldsm4(uint32_t* r, uint32_t addr) {
    asm volatile("ldmatrix.sync.aligned.m8n8.x4.shared.b16 {%0,%1,%2,%3}, [%4];"
                 : "=r"(r[0]), "=r"(r[1]), "=r"(r[2]), "=r"(r[3]) : "r"(addr));
}
static __device__ __forceinline__ void mma16816(float* c, const uint32_t* a, const uint32_t* b) {
    asm volatile("mma.sync.aligned.m16n8k16.row.col.f32.f16.f16.f32 "
                 "{%0,%1,%2,%3}, {%4,%5,%6,%7}, {%8,%9}, {%0,%1,%2,%3};"
                 : "+f"(c[0]), "+f"(c[1]), "+f"(c[2]), "+f"(c[3])
                 : "r"(a[0]), "r"(a[1]), "r"(a[2]), "r"(a[3]), "r"(b[0]), "r"(b[1]));
}
static __device__ __forceinline__ void cp16(uint32_t dst, const void* src) {
    asm volatile("cp.async.cg.shared.global [%0], [%1], 16;" :: "r"(dst), "l"(src) : "memory");
}
#define CP_COMMIT asm volatile("cp.async.commit_group;" ::: "memory")
#define CP_WAIT0  asm volatile("cp.async.wait_group 0;" ::: "memory")

// ============ kernel 0: fused weight + activation conversion (fp32 -> fp16, swizzled) ============
// blocks [0, 576): weights (run first, finish in wave 1); blocks [576, 19008): activations
__global__ __launch_bounds__(256)
void caps_conv(const float* __restrict__ x_img,
               const float* __restrict__ x_capt,
               const float* __restrict__ x_dct,
               const float* __restrict__ w_img,
               const float* __restrict__ w_capt,
               const float* __restrict__ w_dct)
{
    if (blockIdx.x == 0 && threadIdx.x == 0) g_ctr = GRID_P;   // reset work counter

    if (blockIdx.x < 576) {
        // ---- weights ----
        int gt  = blockIdx.x * 256 + threadIdx.x;     // [0, 147456)
        int mod = gt / 49152;
        int r   = gt % 49152;
        int n   = r / 96;
        int k8  = r % 96;
        const float* W = (mod == 0) ? w_img : (mod == 1) ? w_capt : w_dct;
        int wrow = ((n & 7) << 6) | (n >> 3);         // W row for col n = r*8 + c
        const float4* src = (const float4*)(W + (size_t)wrow * IN_CH + k8 * 8);
        float4 p = src[0], q = src[1];
        __half2 h0 = __float22half2_rn(make_float2(p.x, p.y));
        __half2 h1 = __float22half2_rn(make_float2(p.z, p.w));
        __half2 h2 = __float22half2_rn(make_float2(q.x, q.y));
        __half2 h3 = __float22half2_rn(make_float2(q.z, q.w));
        int ntile = n >> 7, rloc = n & 127;
        int kch = k8 >> 3, cell = k8 & 7;
        uint32_t off = SWZ((uint32_t)(rloc * 128 + cell * 16));
        unsigned char* dst = g_Bscr + (size_t)((mod * 4 + ntile) * 12 + kch) * 16384 + off;
        *(uint4*)dst = make_uint4(*(uint32_t*)&h0, *(uint32_t*)&h1, *(uint32_t*)&h2, *(uint32_t*)&h3);
    } else {
        // ---- activations ----
        int gt  = (blockIdx.x - 576) * 256 + threadIdx.x;   // [0, 4718592)
        int mod = gt / 1572864;
        int r   = gt % 1572864;
        int b   = r / 96;
        int k8  = r % 96;
        const float* X = (mod == 0) ? x_img : (mod == 1) ? x_capt : x_dct;
        const float4* src = (const float4*)(X + (size_t)b * IN_CH + k8 * 8);
        float4 p = src[0], q = src[1];
        __half2 h0 = __float22half2_rn(make_float2(p.x, p.y));
        __half2 h1 = __float22half2_rn(make_float2(p.z, p.w));
        __half2 h2 = __float22half2_rn(make_float2(q.x, q.y));
        __half2 h3 = __float22half2_rn(make_float2(q.z, q.w));
        int mtile = b >> 7, rloc = b & 127;
        int kch = k8 >> 3, cell = k8 & 7;
        uint32_t off = SWZ((uint32_t)(rloc * 128 + cell * 16));
        unsigned char* dst = g_Ascr + (size_t)(((mod * 128 + mtile) * 12) + kch) * 16384 + off;
        *(uint4*)dst = make_uint4(*(uint32_t*)&h0, *(uint32_t*)&h1, *(uint32_t*)&h2, *(uint32_t*)&h3);
    }
}

// tile decode: t in [0, NT): mod = t/512, mtile = (t%512)>>2, ntile = t&3
static __device__ __forceinline__ void decode_tile(int t,
    const unsigned char*& aG, const unsigned char*& bG, int& b0, int& n0, int& mod)
{
    mod = t / 512;
    int rem = t - mod * 512;
    int mtile = rem >> 2, ntile = rem & 3;
    aG = g_Ascr + (size_t)((mod * 128 + mtile) * 12) * 16384;
    bG = g_Bscr + (size_t)((mod * 4 + ntile) * 12) * 16384;
    b0 = mtile * BM;
    n0 = ntile * BN;
}

// ============ kernel 1: persistent fp16 mma.sync GEMM + bias + squash ============
// 4 warps, warp tile 64x64, 3 CTAs/SM, 2-stage pipeline, atomic work-stealing
__global__ __launch_bounds__(128, 3)
void caps_gemm(const float* __restrict__ b_img,
               const float* __restrict__ b_capt,
               const float* __restrict__ b_dct,
               float* __restrict__ out)
{
    extern __shared__ __align__(1024) unsigned char smem[];
    const uint32_t sb = s2u(smem);
    float* biasCur = (float*)smem;
    float* biasNxt = (float*)(smem + 512);
    volatile int* nextTS = (volatile int*)(smem + 1024);

    const int tid  = threadIdx.x;
    const int lane = tid & 31;
    const int w    = tid >> 5;
    const int wm   = w & 1;            // 2 warps over M (64 rows each)
    const int wn   = w >> 1;           // 2 warps over N (64 cols each)

    // ldsm consumer bases (tile-independent)
    const uint32_t aXor  = (uint32_t)((lane & 7) << 4);
    const uint32_t aRowB = (uint32_t)((wm * 64 + (lane & 15)) * 128);
    const uint32_t aCell = (uint32_t)(((lane >> 4) & 1) * 16);
    const uint32_t bXor  = aXor;
    const uint32_t bRowB = (uint32_t)((wn * 64 + (lane & 7) + ((lane & 16) ? 8 : 0)) * 128);
    const uint32_t bCell = (uint32_t)((lane & 8) ? 16 : 0);

    int t = blockIdx.x;                // first tile statically assigned
    const unsigned char *aG, *bG;
    int b0, n0, mod;
    decode_tile(t, aG, bG, b0, n0, mod);
    {
        const float* Bv = (mod == 0) ? b_img : (mod == 1) ? b_capt : b_dct;
        int n = n0 + tid; biasCur[tid] = Bv[((n & 7) << 6) + (n >> 3)];
    }

    // ---- prologue: stage 0 <- chunk 0 of first tile ----
    {
        uint32_t dst = sb + SM_STG(0);
        #pragma unroll
        for (int j = 0; j < 8; ++j) {
            cp16(dst + tid * 16 + j * 2048,         aG + tid * 16 + j * 2048);
            cp16(dst + OFF_B + tid * 16 + j * 2048, bG + tid * 16 + j * 2048);
        }
        CP_COMMIT;
    }
    CP_WAIT0;
    __syncthreads();

    int stage = 0;
    for (;;) {
        float acc[4][8][4];
        #pragma unroll
        for (int i = 0; i < 4; ++i)
            #pragma unroll
            for (int j = 0; j < 8; ++j)
                #pragma unroll
                for (int k = 0; k < 4; ++k) acc[i][j][k] = 0.f;

        int nt = NT;
        int nb0 = 0, nn0 = 0, nmod = 0;
        const unsigned char *aN = aG, *bN = bG;

        for (int i = 0; i < NCHUNK; ++i) {
            if (i == 0 && tid == 0) *nextTS = atomicAdd(&g_ctr, 1);

            bool issued = false;
            if (i + 1 < NCHUNK) {
                uint32_t dst = sb + SM_STG(stage ^ 1);
                const unsigned char* sa = aG + (size_t)(i + 1) * 16384;
                const unsigned char* sbp = bG + (size_t)(i + 1) * 16384;
                #pragma unroll
                for (int j = 0; j < 8; ++j) {
                    cp16(dst + tid * 16 + j * 2048,         sa + tid * 16 + j * 2048);
                    cp16(dst + OFF_B + tid * 16 + j * 2048, sbp + tid * 16 + j * 2048);
                }
                CP_COMMIT;
                issued = true;
            } else {
                nt = *nextTS;
                if (nt < NT) {
                    decode_tile(nt, aN, bN, nb0, nn0, nmod);
                    uint32_t dst = sb + SM_STG(stage ^ 1);
                    #pragma unroll
                    for (int j = 0; j < 8; ++j) {
                        cp16(dst + tid * 16 + j * 2048,         aN + tid * 16 + j * 2048);
                        cp16(dst + OFF_B + tid * 16 + j * 2048, bN + tid * 16 + j * 2048);
                    }
                    CP_COMMIT;
                    // stage next tile's bias into the spare slot (no hazard: epilogue reads biasCur)
                    const float* Bv = (nmod == 0) ? b_img : (nmod == 1) ? b_capt : b_dct;
                    int n = nn0 + tid;
                    biasNxt[tid] = Bv[((n & 7) << 6) + (n >> 3)];
                    issued = true;
                }
            }

            // ---- compute chunk i from current stage ----
            const uint32_t stg = sb + SM_STG(stage);
            #pragma unroll
            for (int st = 0; st < 4; ++st) {
                const uint32_t sx = (uint32_t)(st << 5);
                uint32_t af[4][4];
                #pragma unroll
                for (int mt = 0; mt < 4; ++mt)
                    ldsm4(af[mt], stg + aRowB + mt * 2048 + ((sx + aCell) ^ aXor));
                #pragma unroll
                for (int g = 0; g < 4; ++g) {
                    uint32_t bf[4];
                    ldsm4(bf, stg + OFF_B + bRowB + g * 2048 + ((sx + bCell) ^ bXor));
                    #pragma unroll
                    for (int half = 0; half < 2; ++half) {
                        const uint32_t* BH = &bf[half * 2];
                        #pragma unroll
                        for (int mt = 0; mt < 4; ++mt)
                            mma16816(acc[mt][2 * g + half], af[mt], BH);
                    }
                }
            }

            if (issued) {
                CP_WAIT0;
                __syncthreads();
                stage ^= 1;
            }
        }

        // ---- epilogue: bias + squash ----
        const int t4 = lane & 3, g8 = lane >> 2;
        #pragma unroll
        for (int mt = 0; mt < 4; ++mt) {
            const int row0 = b0 + wm * 64 + mt * 16 + g8;
            #pragma unroll
            for (int ntj = 0; ntj < 8; ++ntj) {
                float* c = acc[mt][ntj];
                const int cl = wn * 64 + ntj * 8 + 2 * t4;
                const float bx = biasCur[cl], by = biasCur[cl + 1];
                float u0 = c[0] + bx, u1 = c[1] + by;
                float u2 = c[2] + bx, u3 = c[3] + by;
                float s0 = u0 * u0 + u1 * u1;
                float s1 = u2 * u2 + u3 * u3;
                s0 += __shfl_xor_sync(0xffffffffu, s0, 1);
                s0 += __shfl_xor_sync(0xffffffffu, s0, 2);
                s1 += __shfl_xor_sync(0xffffffffu, s1, 1);
                s1 += __shfl_xor_sync(0xffffffffu, s1, 2);
                float sc0 = s0 / ((1.0f + s0) * sqrtf(s0 + 1e-7f));
                float sc1 = s1 / ((1.0f + s1) * sqrtf(s1 + 1e-7f));
                float* p0 = out + (size_t)row0 * OUT_ROW + mod * 512 + n0 + cl;
                float* p1 = p0 + 8 * OUT_ROW;
                *(float2*)p0 = make_float2(u0 * sc0, u1 * sc0);
                *(float2*)p1 = make_float2(u2 * sc1, u3 * sc1);
            }
        }

        if (nt >= NT) break;
        __syncthreads();                       // epilogue bias reads done
        biasCur[tid] = biasNxt[tid];           // smem->smem, cheap
        t = nt; aG = aN; bG = bN; b0 = nb0; n0 = nn0; mod = nmod;
        __syncthreads();                       // biasCur ready for all warps
    }
}

extern "C" void kernel_launch(void* const* d_in, const int* in_sizes, int n_in,
                              void* d_out, int out_size)
{
    const float* x_img  = (const float*)d_in[0];
    const float* x_capt = (const float*)d_in[1];
    const float* x_dct  = (const float*)d_in[2];
    const float* w_img  = (const float*)d_in[3];
    const float* b_img  = (const float*)d_in[4];
    const float* w_capt = (const float*)d_in[5];
    const float* b_capt = (const float*)d_in[6];
    const float* w_dct  = (const float*)d_in[7];
    const float* b_dct  = (const float*)d_in[8];
    float* out = (float*)d_out;

    cudaFuncSetAttribute(caps_gemm, cudaFuncAttributeMaxDynamicSharedMemorySize, SMEM_TOTAL);

    caps_conv<<<19008, 256>>>(x_img, x_capt, x_dct, w_img, w_capt, w_dct);

    caps_gemm<<<GRID_P, 128, SMEM_TOTAL>>>(b_img, b_capt, b_dct, out);
}